// round 12
// baseline (speedup 1.0000x reference)
#include <cuda_runtime.h>
#include <cuda_fp16.h>
#include <cstdint>

// ===========================================================================
// B=8, S=2048, D=1024 attention. fp16 mma.sync(m16n8k16) + cp.async pipeline.
// R12: CTA tile 128x256 (256 thr, 8 warps, warp 64x64) to cut L2 traffic 25%.
// ===========================================================================

static __device__ __half g_qh [8ull * 2048ull * 1024ull];
static __device__ __half g_kh [8ull * 2048ull * 1024ull];
static __device__ __half g_vh [8ull * 2048ull * 1024ull];
static __device__ __half g_Wqh[1024ull * 1024ull];
static __device__ __half g_Wkh[1024ull * 1024ull];
static __device__ __half g_Wvh[1024ull * 1024ull];
static __device__ __half g_wqh[8ull * 2048ull * 1024ull];
static __device__ __half g_wkh[8ull * 2048ull * 1024ull];
static __device__ __half g_wvh[8ull * 2048ull * 1024ull];
static __device__ __half g_wvT[8ull * 1024ull * 2048ull];
static __device__ __half g_att[8ull * 2048ull * 2048ull];

__device__ __forceinline__ uint32_t smem_u32(const void* p) {
    uint32_t a;
    asm("{ .reg .u64 t; cvta.to.shared.u64 t, %1; cvt.u32.u64 %0, t; }"
        : "=r"(a) : "l"(p));
    return a;
}

__device__ __forceinline__ void cp16(uint32_t s, const void* g) {
    asm volatile("cp.async.cg.shared.global [%0], [%1], 16;" :: "r"(s), "l"(g));
}
#define CP_COMMIT() asm volatile("cp.async.commit_group;" ::: "memory")
#define CP_WAIT1()  asm volatile("cp.async.wait_group 1;" ::: "memory")

#define LDSM_X4(r, a)                                                        \
    asm volatile("ldmatrix.sync.aligned.m8n8.x4.shared.b16 {%0,%1,%2,%3}, [%4];" \
        : "=r"((r)[0]), "=r"((r)[1]), "=r"((r)[2]), "=r"((r)[3]) : "r"(a))

__device__ __forceinline__ void mma_f16(float* d, const uint32_t* a,
                                        const uint32_t* b) {
    asm volatile(
        "mma.sync.aligned.m16n8k16.row.col.f32.f16.f16.f32 "
        "{%0,%1,%2,%3}, {%4,%5,%6,%7}, {%8,%9}, {%0,%1,%2,%3};\n"
        : "+f"(d[0]), "+f"(d[1]), "+f"(d[2]), "+f"(d[3])
        : "r"(a[0]), "r"(a[1]), "r"(a[2]), "r"(a[3]), "r"(b[0]), "r"(b[1]));
}

// SMEM: 3 stages x (A 16KB + B 32KB) = 144 KB
static constexpr int STAGE  = 49152;
static constexpr int SMEMSZ = 3 * STAGE;

// ---------------------------------------------------------------------------
// Core: C = alpha*(A @ B^T) [+bias cols] [+mask]; A:[*,K] B:[*,K] fp16 NT.
// CTA 128x256, 8 warps (wm = wid&1 m-half, wn = wid>>2.. see below),
// warp tile 64x64, K-chunk 64, 3-stage cp.async ring.
// smem rows: A 128 x 128B, B 256 x 128B; 16B chunk c at (c ^ (row&7)).
// Both operands via NON-trans ldmatrix (B stored [n][k] == col-major KxN).
// Fragments double-buffered in registers across the 4 kk sub-steps.
// ---------------------------------------------------------------------------
template <bool HOUT>
__device__ __forceinline__ void gemm_core(
    const __half* __restrict__ A, const __half* __restrict__ B,
    void* __restrict__ Cv, int N, int K, float alpha,
    const float* __restrict__ bias,
    const float* __restrict__ mask, int ldMask,
    int m0, int n0)
{
    extern __shared__ char smem[];
    const uint32_t sb = smem_u32(smem);
    const int tid  = threadIdx.x;
    const int lane = tid & 31;
    const int wid  = tid >> 5;
    const int wm   = wid & 1;     // m half   (0..1) -> 64 rows
    const int wn   = wid >> 1;    // n quarter (0..3) -> 64 cols

    float acc[4][8][4];
#pragma unroll
    for (int i = 0; i < 4; ++i)
#pragma unroll
        for (int j = 0; j < 8; ++j)
#pragma unroll
            for (int l = 0; l < 4; ++l) acc[i][j][l] = 0.f;

    const int KT = K >> 6;

    auto stage = [&](int it) {
        const int buf = it % 3;
        const uint32_t sA = sb + buf * STAGE;
        const uint32_t sB = sA + 16384;
        const __half* Ab = A + (size_t)m0 * K + it * 64;
        const __half* Bb = B + (size_t)n0 * K + it * 64;
#pragma unroll
        for (int i = 0; i < 4; ++i) {          // A: 128 rows
            const int f = tid + (i << 8);
            const int r = f >> 3, c = f & 7;
            cp16(sA + r * 128 + ((c ^ (r & 7)) << 4), Ab + (size_t)r * K + c * 8);
        }
#pragma unroll
        for (int i = 0; i < 8; ++i) {          // B: 256 rows
            const int f = tid + (i << 8);
            const int r = f >> 3, c = f & 7;
            cp16(sB + r * 128 + ((c ^ (r & 7)) << 4), Bb + (size_t)r * K + c * 8);
        }
    };

    stage(0); CP_COMMIT();
    stage(1); CP_COMMIT();

    // per-lane ldmatrix row/chunk selectors (both operands non-trans)
    const int rowA = (lane & 7) + ((lane >> 3) & 1) * 8;
    const int cselA = lane >> 4;
    const int rowB = (lane & 7) + ((lane >> 4) << 3);
    const int cselB = (lane >> 3) & 1;

    uint32_t af[2][4][4], bf[2][4][4];

    for (int it = 0; it < KT; ++it) {
        CP_WAIT1();
        __syncthreads();
        if (it + 2 < KT) stage(it + 2);
        CP_COMMIT();

        const uint32_t aB = sb + (it % 3) * STAGE;
        const uint32_t bB = aB + 16384;

        // prime kk = 0 fragments
#pragma unroll
        for (int mi = 0; mi < 4; ++mi) {
            const int r = wm * 64 + mi * 16 + rowA;
            LDSM_X4(af[0][mi], aB + r * 128 + ((cselA ^ (r & 7)) << 4));
        }
#pragma unroll
        for (int np = 0; np < 4; ++np) {
            const int r = wn * 64 + np * 16 + rowB;
            LDSM_X4(bf[0][np], bB + r * 128 + ((cselB ^ (r & 7)) << 4));
        }

#pragma unroll
        for (int kk = 0; kk < 4; ++kk) {
            const int cur = kk & 1, nxt = cur ^ 1;
            if (kk < 3) {                // prefetch kk+1 while mma'ing kk
                const int ch = 2 * (kk + 1);
#pragma unroll
                for (int mi = 0; mi < 4; ++mi) {
                    const int r = wm * 64 + mi * 16 + rowA;
                    LDSM_X4(af[nxt][mi],
                            aB + r * 128 + (((ch + cselA) ^ (r & 7)) << 4));
                }
#pragma unroll
                for (int np = 0; np < 4; ++np) {
                    const int r = wn * 64 + np * 16 + rowB;
                    LDSM_X4(bf[nxt][np],
                            bB + r * 128 + (((ch + cselB) ^ (r & 7)) << 4));
                }
            }
#pragma unroll
            for (int mi = 0; mi < 4; ++mi)
#pragma unroll
                for (int ni = 0; ni < 8; ++ni)
                    mma_f16(acc[mi][ni], af[cur][mi],
                            &bf[cur][ni >> 1][(ni & 1) * 2]);
        }
        // no trailing barrier: next iteration's CP_WAIT1+__syncthreads orders
        // these smem reads against the stage() that overwrites this buffer.
    }

    // ---- epilogue ----
    const int mrow = m0 + wm * 64 + (lane >> 2);
    const int ncol = n0 + wn * 64 + 2 * (lane & 3);
#pragma unroll
    for (int mi = 0; mi < 4; ++mi) {
#pragma unroll
        for (int h = 0; h < 2; ++h) {
            const int m = mrow + mi * 16 + h * 8;
#pragma unroll
            for (int ni = 0; ni < 8; ++ni) {
                const int n = ncol + ni * 8;
                float x = acc[mi][ni][h * 2 + 0] * alpha;
                float y = acc[mi][ni][h * 2 + 1] * alpha;
                if (bias) { x += bias[n]; y += bias[n + 1]; }
                if (mask) {
                    const float2 mm = *(const float2*)
                        (mask + (size_t)m * ldMask + n);
                    x += mm.x; y += mm.y;
                }
                if (HOUT) {
                    *(__half2*)((__half*)Cv + (size_t)m * N + n) =
                        __floats2half2_rn(x, y);
                } else {
                    *(float2*)((float*)Cv + (size_t)m * N + n) =
                        make_float2(x, y);
                }
            }
        }
    }
}

// ---- wrappers -------------------------------------------------------------
__global__ __launch_bounds__(256, 1)
void proj_kernel(const __half* q, const __half* k, const __half* v,
                 const __half* Wq, const __half* Wk, const __half* Wv,
                 const float* bq, const float* bk, const float* bv,
                 __half* wq, __half* wk, __half* wv)
{
    const int z = blockIdx.z;
    const __half* A = z == 0 ? q : z == 1 ? k : v;
    const __half* B = z == 0 ? Wq : z == 1 ? Wk : Wv;
    const float* bi = z == 0 ? bq : z == 1 ? bk : bv;
    __half*      C = z == 0 ? wq : z == 1 ? wk : wv;
    gemm_core<true>(A, B, C, 1024, 1024, 1.f, bi, nullptr, 0,
                    blockIdx.y * 128, blockIdx.x * 256);
}

__global__ __launch_bounds__(256, 1)
void scores_kernel(const __half* wq, const __half* wk, __half* att,
                   const float* mask)
{
    const size_t pS = 2048ull * 1024ull, aS = 2048ull * 2048ull;
    gemm_core<true>(wq + blockIdx.z * pS, wk + blockIdx.z * pS,
                    att + blockIdx.z * aS, 2048, 1024, 1.f / 32.f,
                    nullptr, mask, 2048,
                    blockIdx.y * 128, blockIdx.x * 256);
}

__global__ __launch_bounds__(256, 1)
void out_kernel(const __half* att, const __half* wvT, float* out)
{
    const size_t aS = 2048ull * 2048ull, tS = 1024ull * 2048ull,
                 oS = 2048ull * 1024ull;
    gemm_core<false>(att + blockIdx.z * aS, wvT + blockIdx.z * tS,
                     out + blockIdx.z * oS, 1024, 2048, 1.f,
                     nullptr, nullptr, 0,
                     blockIdx.y * 128, blockIdx.x * 256);
}

// ---- fp32 -> fp16 convert -------------------------------------------------
__global__ __launch_bounds__(256)
void f2h_kernel(const float4* __restrict__ src, __half2* __restrict__ dst)
{
    const int i = blockIdx.x * 256 + threadIdx.x;
    const float4 v = src[i];
    dst[2 * i + 0] = __floats2half2_rn(v.x, v.y);
    dst[2 * i + 1] = __floats2half2_rn(v.z, v.w);
}

// ---- fp16 transpose: out[b][d][s] = in[b][s][d] ---------------------------
__global__ __launch_bounds__(256)
void transpose_h(const __half* __restrict__ in, __half* __restrict__ out)
{
    __shared__ __half tile[32][33];
    const int S = 2048, D = 1024;
    const size_t bo = (size_t)blockIdx.z * S * D;
    const int d0 = blockIdx.x * 32;
    const int s0 = blockIdx.y * 32;
    const int tx = threadIdx.x & 31;
    const int ty = threadIdx.x >> 5;
#pragma unroll
    for (int i = 0; i < 4; ++i)
        tile[ty + i * 8][tx] = in[bo + (size_t)(s0 + ty + i * 8) * D + d0 + tx];
    __syncthreads();
#pragma unroll
    for (int i = 0; i < 4; ++i)
        out[bo + (size_t)(d0 + ty + i * 8) * S + s0 + tx] = tile[tx][ty + i * 8];
}

// ---- softmax: rows of 2048 fp16, fp32 math --------------------------------
__global__ __launch_bounds__(256)
void softmax_h(__half* __restrict__ att)
{
    __half* p = att + (size_t)blockIdx.x * 2048;
    const int tid = threadIdx.x;
    const int lane = tid & 31;
    const int warp = tid >> 5;

    uint4 raw = ((const uint4*)p)[tid];      // 8 halves
    float2 f0 = __half22float2(*(__half2*)&raw.x);
    float2 f1 = __half22float2(*(__half2*)&raw.y);
    float2 f2 = __half22float2(*(__half2*)&raw.z);
    float2 f3 = __half22float2(*(__half2*)&raw.w);
    float x[8] = {f0.x, f0.y, f1.x, f1.y, f2.x, f2.y, f3.x, f3.y};

    __shared__ float sm[8];

    float mx = x[0];
#pragma unroll
    for (int i = 1; i < 8; ++i) mx = fmaxf(mx, x[i]);
#pragma unroll
    for (int o = 16; o > 0; o >>= 1)
        mx = fmaxf(mx, __shfl_xor_sync(0xffffffffu, mx, o));
    if (lane == 0) sm[warp] = mx;
    __syncthreads();
    if (tid == 0) {
        float t = sm[0];
#pragma unroll
        for (int i = 1; i < 8; ++i) t = fmaxf(t, sm[i]);
        sm[0] = t;
    }
    __syncthreads();
    mx = sm[0];
    __syncthreads();

    float s = 0.f;
#pragma unroll
    for (int i = 0; i < 8; ++i) { x[i] = __expf(x[i] - mx); s += x[i]; }
#pragma unroll
    for (int o = 16; o > 0; o >>= 1)
        s += __shfl_xor_sync(0xffffffffu, s, o);
    if (lane == 0) sm[warp] = s;
    __syncthreads();
    if (tid == 0) {
        float t = 0.f;
#pragma unroll
        for (int i = 0; i < 8; ++i) t += sm[i];
        sm[0] = t;
    }
    __syncthreads();
    const float inv = 1.f / sm[0];

    uint4 o;
    *(__half2*)&o.x = __floats2half2_rn(x[0] * inv, x[1] * inv);
    *(__half2*)&o.y = __floats2half2_rn(x[2] * inv, x[3] * inv);
    *(__half2*)&o.z = __floats2half2_rn(x[4] * inv, x[5] * inv);
    *(__half2*)&o.w = __floats2half2_rn(x[6] * inv, x[7] * inv);
    ((uint4*)p)[tid] = o;
}

// ---------------------------------------------------------------------------

extern "C" void kernel_launch(void* const* d_in, const int* in_sizes, int n_in,
                              void* d_out, int out_size)
{
    const float* q    = (const float*)d_in[0];
    const float* k    = (const float*)d_in[1];
    const float* v    = (const float*)d_in[2];
    const float* mask = (const float*)d_in[3];
    const float* Wq   = (const float*)d_in[4];
    const float* bq   = (const float*)d_in[5];
    const float* Wk   = (const float*)d_in[6];
    const float* bk   = (const float*)d_in[7];
    const float* Wv   = (const float*)d_in[8];
    const float* bv   = (const float*)d_in[9];
    float* out = (float*)d_out;

    __half *qh, *kh, *vh, *Wqh, *Wkh, *Wvh, *wqh, *wkh, *wvh, *wvT, *att;
    cudaGetSymbolAddress((void**)&qh,  g_qh);
    cudaGetSymbolAddress((void**)&kh,  g_kh);
    cudaGetSymbolAddress((void**)&vh,  g_vh);
    cudaGetSymbolAddress((void**)&Wqh, g_Wqh);
    cudaGetSymbolAddress((void**)&Wkh, g_Wkh);
    cudaGetSymbolAddress((void**)&Wvh, g_Wvh);
    cudaGetSymbolAddress((void**)&wqh, g_wqh);
    cudaGetSymbolAddress((void**)&wkh, g_wkh);
    cudaGetSymbolAddress((void**)&wvh, g_wvh);
    cudaGetSymbolAddress((void**)&wvT, g_wvT);
    cudaGetSymbolAddress((void**)&att, g_att);

    cudaFuncSetAttribute(proj_kernel,
        cudaFuncAttributeMaxDynamicSharedMemorySize, SMEMSZ);
    cudaFuncSetAttribute(scores_kernel,
        cudaFuncAttributeMaxDynamicSharedMemorySize, SMEMSZ);
    cudaFuncSetAttribute(out_kernel,
        cudaFuncAttributeMaxDynamicSharedMemorySize, SMEMSZ);

    const int B = 8, S = 2048, D = 1024;
    const int BSD4 = B * S * D / 4;
    const int DD4  = D * D / 4;

    // converts
    f2h_kernel<<<BSD4 / 256, 256>>>((const float4*)q, (__half2*)qh);
    f2h_kernel<<<BSD4 / 256, 256>>>((const float4*)k, (__half2*)kh);
    f2h_kernel<<<BSD4 / 256, 256>>>((const float4*)v, (__half2*)vh);
    f2h_kernel<<<DD4  / 256, 256>>>((const float4*)Wq, (__half2*)Wqh);
    f2h_kernel<<<DD4  / 256, 256>>>((const float4*)Wk, (__half2*)Wkh);
    f2h_kernel<<<DD4  / 256, 256>>>((const float4*)Wv, (__half2*)Wvh);

    // projections (z = 0,1,2)
    {
        dim3 grid(D / 256, B * S / 128, 3);
        proj_kernel<<<grid, 256, SMEMSZ>>>(qh, kh, vh, Wqh, Wkh, Wvh,
                                           bq, bk, bv, wqh, wkh, wvh);
    }

    // wvT
    {
        dim3 grid(D / 32, S / 32, B);
        transpose_h<<<grid, 256>>>(wvh, wvT);
    }

    // scores
    {
        dim3 grid(S / 256, S / 128, B);
        scores_kernel<<<grid, 256, SMEMSZ>>>(wqh, wkh, att, mask);
    }

    // softmax
    softmax_h<<<B * S, 256>>>(att);

    // output
    {
        dim3 grid(D / 256, S / 128, B);
        out_kernel<<<grid, 256, SMEMSZ>>>(att, wvT, out);
    }
}

// round 15
// speedup vs baseline: 1.1865x; 1.1865x over previous
#include <cuda_runtime.h>
#include <cuda_fp16.h>
#include <cstdint>

// ===========================================================================
// B=8, S=2048, D=1024 attention. fp16 mma.sync(m16n8k16) + cp.async pipeline.
// R13: revert to R11 GEMM core (128x128, 2 CTA/SM); batch f2h converts.
// ===========================================================================

static __device__ __half g_qh [8ull * 2048ull * 1024ull];
static __device__ __half g_kh [8ull * 2048ull * 1024ull];
static __device__ __half g_vh [8ull * 2048ull * 1024ull];
static __device__ __half g_Wqh[1024ull * 1024ull];
static __device__ __half g_Wkh[1024ull * 1024ull];
static __device__ __half g_Wvh[1024ull * 1024ull];
static __device__ __half g_wqh[8ull * 2048ull * 1024ull];
static __device__ __half g_wkh[8ull * 2048ull * 1024ull];
static __device__ __half g_wvh[8ull * 2048ull * 1024ull];
static __device__ __half g_wvT[8ull * 1024ull * 2048ull];
static __device__ __half g_att[8ull * 2048ull * 2048ull];

__device__ __forceinline__ uint32_t smem_u32(const void* p) {
    uint32_t a;
    asm("{ .reg .u64 t; cvta.to.shared.u64 t, %1; cvt.u32.u64 %0, t; }"
        : "=r"(a) : "l"(p));
    return a;
}

__device__ __forceinline__ void cp16(uint32_t s, const void* g) {
    asm volatile("cp.async.cg.shared.global [%0], [%1], 16;" :: "r"(s), "l"(g));
}
#define CP_COMMIT() asm volatile("cp.async.commit_group;" ::: "memory")
#define CP_WAIT1()  asm volatile("cp.async.wait_group 1;" ::: "memory")

#define LDSM_X4(r, a)                                                        \
    asm volatile("ldmatrix.sync.aligned.m8n8.x4.shared.b16 {%0,%1,%2,%3}, [%4];" \
        : "=r"((r)[0]), "=r"((r)[1]), "=r"((r)[2]), "=r"((r)[3]) : "r"(a))

__device__ __forceinline__ void mma_f16(float* d, const uint32_t* a,
                                        const uint32_t* b) {
    asm volatile(
        "mma.sync.aligned.m16n8k16.row.col.f32.f16.f16.f32 "
        "{%0,%1,%2,%3}, {%4,%5,%6,%7}, {%8,%9}, {%0,%1,%2,%3};\n"
        : "+f"(d[0]), "+f"(d[1]), "+f"(d[2]), "+f"(d[3])
        : "r"(a[0]), "r"(a[1]), "r"(a[2]), "r"(a[3]), "r"(b[0]), "r"(b[1]));
}

// SMEM: 3 stages x (A 16KB + B 16KB) = 96 KB
static constexpr int STAGE  = 32768;
static constexpr int SMEMSZ = 3 * STAGE;

// ---------------------------------------------------------------------------
// Core: C = alpha*(A @ B^T) [+bias cols] [+mask]; A:[*,K] B:[*,K] fp16 NT.
// CTA 128x128, warp 64x64, K-chunk 64, 3-stage cp.async ring.
// smem row layout: 128 rows x 128B (64 halves), 16B chunk c at (c ^ (row&7)).
// Both operands via NON-trans ldmatrix (B stored [n][k] == col-major KxN).
// Fragments double-buffered in registers across the 4 kk sub-steps.
// ---------------------------------------------------------------------------
template <bool HOUT>
__device__ __forceinline__ void gemm_core(
    const __half* __restrict__ A, const __half* __restrict__ B,
    void* __restrict__ Cv, int N, int K, float alpha,
    const float* __restrict__ bias,
    const float* __restrict__ mask, int ldMask,
    int m0, int n0)
{
    extern __shared__ char smem[];
    const uint32_t sb = smem_u32(smem);
    const int tid  = threadIdx.x;
    const int lane = tid & 31;
    const int wid  = tid >> 5;
    const int wm   = wid & 1;
    const int wn   = wid >> 1;

    float acc[4][8][4];
#pragma unroll
    for (int i = 0; i < 4; ++i)
#pragma unroll
        for (int j = 0; j < 8; ++j)
#pragma unroll
            for (int l = 0; l < 4; ++l) acc[i][j][l] = 0.f;

    const int KT = K >> 6;

    auto stage = [&](int it) {
        const int buf = it % 3;
        const uint32_t sA = sb + buf * STAGE;
        const uint32_t sB = sA + 16384;
        const __half* Ab = A + (size_t)m0 * K + it * 64;
        const __half* Bb = B + (size_t)n0 * K + it * 64;
#pragma unroll
        for (int i = 0; i < 8; ++i) {
            const int f = tid + (i << 7);
            const int r = f >> 3, c = f & 7;
            const uint32_t off = r * 128 + ((c ^ (r & 7)) << 4);
            cp16(sA + off, Ab + (size_t)r * K + c * 8);
            cp16(sB + off, Bb + (size_t)r * K + c * 8);
        }
    };

    stage(0); CP_COMMIT();
    stage(1); CP_COMMIT();

    // per-lane ldmatrix row/chunk selectors (both operands non-trans)
    const int rowA = (lane & 7) + ((lane >> 3) & 1) * 8;
    const int cselA = lane >> 4;
    const int rowB = (lane & 7) + ((lane >> 4) << 3);
    const int cselB = (lane >> 3) & 1;

    uint32_t af[2][4][4], bf[2][4][4];

    for (int it = 0; it < KT; ++it) {
        CP_WAIT1();
        __syncthreads();
        if (it + 2 < KT) stage(it + 2);
        CP_COMMIT();

        const uint32_t aB = sb + (it % 3) * STAGE;
        const uint32_t bB = aB + 16384;

        // prime kk = 0 fragments
#pragma unroll
        for (int mi = 0; mi < 4; ++mi) {
            const int r = wm * 64 + mi * 16 + rowA;
            LDSM_X4(af[0][mi], aB + r * 128 + ((cselA ^ (r & 7)) << 4));
        }
#pragma unroll
        for (int np = 0; np < 4; ++np) {
            const int r = wn * 64 + np * 16 + rowB;
            LDSM_X4(bf[0][np], bB + r * 128 + ((cselB ^ (r & 7)) << 4));
        }

#pragma unroll
        for (int kk = 0; kk < 4; ++kk) {
            const int cur = kk & 1, nxt = cur ^ 1;
            if (kk < 3) {                // prefetch kk+1 while mma'ing kk
                const int ch = 2 * (kk + 1);
#pragma unroll
                for (int mi = 0; mi < 4; ++mi) {
                    const int r = wm * 64 + mi * 16 + rowA;
                    LDSM_X4(af[nxt][mi],
                            aB + r * 128 + (((ch + cselA) ^ (r & 7)) << 4));
                }
#pragma unroll
                for (int np = 0; np < 4; ++np) {
                    const int r = wn * 64 + np * 16 + rowB;
                    LDSM_X4(bf[nxt][np],
                            bB + r * 128 + (((ch + cselB) ^ (r & 7)) << 4));
                }
            }
#pragma unroll
            for (int mi = 0; mi < 4; ++mi)
#pragma unroll
                for (int ni = 0; ni < 8; ++ni)
                    mma_f16(acc[mi][ni], af[cur][mi],
                            &bf[cur][ni >> 1][(ni & 1) * 2]);
        }
        // no trailing barrier: next iteration's CP_WAIT1+__syncthreads orders
        // these smem reads against the stage() that overwrites this buffer.
    }

    // ---- epilogue ----
    const int mrow = m0 + wm * 64 + (lane >> 2);
    const int ncol = n0 + wn * 64 + 2 * (lane & 3);
#pragma unroll
    for (int mi = 0; mi < 4; ++mi) {
#pragma unroll
        for (int h = 0; h < 2; ++h) {
            const int m = mrow + mi * 16 + h * 8;
#pragma unroll
            for (int ni = 0; ni < 8; ++ni) {
                const int n = ncol + ni * 8;
                float x = acc[mi][ni][h * 2 + 0] * alpha;
                float y = acc[mi][ni][h * 2 + 1] * alpha;
                if (bias) { x += bias[n]; y += bias[n + 1]; }
                if (mask) {
                    const float2 mm = *(const float2*)
                        (mask + (size_t)m * ldMask + n);
                    x += mm.x; y += mm.y;
                }
                if (HOUT) {
                    *(__half2*)((__half*)Cv + (size_t)m * N + n) =
                        __floats2half2_rn(x, y);
                } else {
                    *(float2*)((float*)Cv + (size_t)m * N + n) =
                        make_float2(x, y);
                }
            }
        }
    }
}

// ---- wrappers -------------------------------------------------------------
__global__ __launch_bounds__(128, 2)
void proj_kernel(const __half* q, const __half* k, const __half* v,
                 const __half* Wq, const __half* Wk, const __half* Wv,
                 const float* bq, const float* bk, const float* bv,
                 __half* wq, __half* wk, __half* wv)
{
    const int z = blockIdx.z;
    const __half* A = z == 0 ? q : z == 1 ? k : v;
    const __half* B = z == 0 ? Wq : z == 1 ? Wk : Wv;
    const float* bi = z == 0 ? bq : z == 1 ? bk : bv;
    __half*      C = z == 0 ? wq : z == 1 ? wk : wv;
    gemm_core<true>(A, B, C, 1024, 1024, 1.f, bi, nullptr, 0,
                    blockIdx.y * 128, blockIdx.x * 128);
}

__global__ __launch_bounds__(128, 2)
void scores_kernel(const __half* wq, const __half* wk, __half* att,
                   const float* mask)
{
    const size_t pS = 2048ull * 1024ull, aS = 2048ull * 2048ull;
    gemm_core<true>(wq + blockIdx.z * pS, wk + blockIdx.z * pS,
                    att + blockIdx.z * aS, 2048, 1024, 1.f / 32.f,
                    nullptr, mask, 2048,
                    blockIdx.y * 128, blockIdx.x * 128);
}

__global__ __launch_bounds__(128, 2)
void out_kernel(const __half* att, const __half* wvT, float* out)
{
    const size_t aS = 2048ull * 2048ull, tS = 1024ull * 2048ull,
                 oS = 2048ull * 1024ull;
    gemm_core<false>(att + blockIdx.z * aS, wvT + blockIdx.z * tS,
                     out + blockIdx.z * oS, 1024, 2048, 1.f,
                     nullptr, nullptr, 0,
                     blockIdx.y * 128, blockIdx.x * 128);
}

// ---- fp32 -> fp16 converts, z-batched -------------------------------------
__global__ __launch_bounds__(256)
void f2h_qkv(const float4* __restrict__ q, const float4* __restrict__ k,
             const float4* __restrict__ v, __half2* __restrict__ qh,
             __half2* __restrict__ kh, __half2* __restrict__ vh)
{
    const int z = blockIdx.z;
    const float4* src = z == 0 ? q : z == 1 ? k : v;
    __half2* dst = z == 0 ? qh : z == 1 ? kh : vh;
    const int i = blockIdx.x * 256 + threadIdx.x;
    const float4 val = src[i];
    dst[2 * i + 0] = __floats2half2_rn(val.x, val.y);
    dst[2 * i + 1] = __floats2half2_rn(val.z, val.w);
}

__global__ __launch_bounds__(256)
void f2h_w(const float4* __restrict__ Wq, const float4* __restrict__ Wk,
           const float4* __restrict__ Wv, __half2* __restrict__ Wqh,
           __half2* __restrict__ Wkh, __half2* __restrict__ Wvh)
{
    const int z = blockIdx.z;
    const float4* src = z == 0 ? Wq : z == 1 ? Wk : Wv;
    __half2* dst = z == 0 ? Wqh : z == 1 ? Wkh : Wvh;
    const int i = blockIdx.x * 256 + threadIdx.x;
    const float4 val = src[i];
    dst[2 * i + 0] = __floats2half2_rn(val.x, val.y);
    dst[2 * i + 1] = __floats2half2_rn(val.z, val.w);
}

// ---- fp16 transpose: out[b][d][s] = in[b][s][d] ---------------------------
__global__ __launch_bounds__(256)
void transpose_h(const __half* __restrict__ in, __half* __restrict__ out)
{
    __shared__ __half tile[32][33];
    const int S = 2048, D = 1024;
    const size_t bo = (size_t)blockIdx.z * S * D;
    const int d0 = blockIdx.x * 32;
    const int s0 = blockIdx.y * 32;
    const int tx = threadIdx.x & 31;
    const int ty = threadIdx.x >> 5;
#pragma unroll
    for (int i = 0; i < 4; ++i)
        tile[ty + i * 8][tx] = in[bo + (size_t)(s0 + ty + i * 8) * D + d0 + tx];
    __syncthreads();
#pragma unroll
    for (int i = 0; i < 4; ++i)
        out[bo + (size_t)(d0 + ty + i * 8) * S + s0 + tx] = tile[tx][ty + i * 8];
}

// ---- softmax: rows of 2048 fp16, fp32 math --------------------------------
__global__ __launch_bounds__(256)
void softmax_h(__half* __restrict__ att)
{
    __half* p = att + (size_t)blockIdx.x * 2048;
    const int tid = threadIdx.x;
    const int lane = tid & 31;
    const int warp = tid >> 5;

    uint4 raw = ((const uint4*)p)[tid];      // 8 halves
    float2 f0 = __half22float2(*(__half2*)&raw.x);
    float2 f1 = __half22float2(*(__half2*)&raw.y);
    float2 f2 = __half22float2(*(__half2*)&raw.z);
    float2 f3 = __half22float2(*(__half2*)&raw.w);
    float x[8] = {f0.x, f0.y, f1.x, f1.y, f2.x, f2.y, f3.x, f3.y};

    __shared__ float sm[8];

    float mx = x[0];
#pragma unroll
    for (int i = 1; i < 8; ++i) mx = fmaxf(mx, x[i]);
#pragma unroll
    for (int o = 16; o > 0; o >>= 1)
        mx = fmaxf(mx, __shfl_xor_sync(0xffffffffu, mx, o));
    if (lane == 0) sm[warp] = mx;
    __syncthreads();
    if (tid == 0) {
        float t = sm[0];
#pragma unroll
        for (int i = 1; i < 8; ++i) t = fmaxf(t, sm[i]);
        sm[0] = t;
    }
    __syncthreads();
    mx = sm[0];
    __syncthreads();

    float s = 0.f;
#pragma unroll
    for (int i = 0; i < 8; ++i) { x[i] = __expf(x[i] - mx); s += x[i]; }
#pragma unroll
    for (int o = 16; o > 0; o >>= 1)
        s += __shfl_xor_sync(0xffffffffu, s, o);
    if (lane == 0) sm[warp] = s;
    __syncthreads();
    if (tid == 0) {
        float t = 0.f;
#pragma unroll
        for (int i = 0; i < 8; ++i) t += sm[i];
        sm[0] = t;
    }
    __syncthreads();
    const float inv = 1.f / sm[0];

    uint4 o;
    *(__half2*)&o.x = __floats2half2_rn(x[0] * inv, x[1] * inv);
    *(__half2*)&o.y = __floats2half2_rn(x[2] * inv, x[3] * inv);
    *(__half2*)&o.z = __floats2half2_rn(x[4] * inv, x[5] * inv);
    *(__half2*)&o.w = __floats2half2_rn(x[6] * inv, x[7] * inv);
    ((uint4*)p)[tid] = o;
}

// ---------------------------------------------------------------------------

extern "C" void kernel_launch(void* const* d_in, const int* in_sizes, int n_in,
                              void* d_out, int out_size)
{
    const float* q    = (const float*)d_in[0];
    const float* k    = (const float*)d_in[1];
    const float* v    = (const float*)d_in[2];
    const float* mask = (const float*)d_in[3];
    const float* Wq   = (const float*)d_in[4];
    const float* bq   = (const float*)d_in[5];
    const float* Wk   = (const float*)d_in[6];
    const float* bk   = (const float*)d_in[7];
    const float* Wv   = (const float*)d_in[8];
    const float* bv   = (const float*)d_in[9];
    float* out = (float*)d_out;

    __half *qh, *kh, *vh, *Wqh, *Wkh, *Wvh, *wqh, *wkh, *wvh, *wvT, *att;
    cudaGetSymbolAddress((void**)&qh,  g_qh);
    cudaGetSymbolAddress((void**)&kh,  g_kh);
    cudaGetSymbolAddress((void**)&vh,  g_vh);
    cudaGetSymbolAddress((void**)&Wqh, g_Wqh);
    cudaGetSymbolAddress((void**)&Wkh, g_Wkh);
    cudaGetSymbolAddress((void**)&Wvh, g_Wvh);
    cudaGetSymbolAddress((void**)&wqh, g_wqh);
    cudaGetSymbolAddress((void**)&wkh, g_wkh);
    cudaGetSymbolAddress((void**)&wvh, g_wvh);
    cudaGetSymbolAddress((void**)&wvT, g_wvT);
    cudaGetSymbolAddress((void**)&att, g_att);

    cudaFuncSetAttribute(proj_kernel,
        cudaFuncAttributeMaxDynamicSharedMemorySize, SMEMSZ);
    cudaFuncSetAttribute(scores_kernel,
        cudaFuncAttributeMaxDynamicSharedMemorySize, SMEMSZ);
    cudaFuncSetAttribute(out_kernel,
        cudaFuncAttributeMaxDynamicSharedMemorySize, SMEMSZ);

    const int B = 8, S = 2048, D = 1024;
    const int BSD4 = B * S * D / 4;
    const int DD4  = D * D / 4;

    // converts (2 z-batched launches instead of 6)
    {
        dim3 grid(BSD4 / 256, 1, 3);
        f2h_qkv<<<grid, 256>>>((const float4*)q, (const float4*)k,
                               (const float4*)v,
                               (__half2*)qh, (__half2*)kh, (__half2*)vh);
    }
    {
        dim3 grid(DD4 / 256, 1, 3);
        f2h_w<<<grid, 256>>>((const float4*)Wq, (const float4*)Wk,
                             (const float4*)Wv,
                             (__half2*)Wqh, (__half2*)Wkh, (__half2*)Wvh);
    }

    // projections (z = 0,1,2)
    {
        dim3 grid(D / 128, B * S / 128, 3);
        proj_kernel<<<grid, 128, SMEMSZ>>>(qh, kh, vh, Wqh, Wkh, Wvh,
                                           bq, bk, bv, wqh, wkh, wvh);
    }

    // wvT
    {
        dim3 grid(D / 32, S / 32, B);
        transpose_h<<<grid, 256>>>(wvh, wvT);
    }

    // scores
    {
        dim3 grid(S / 128, S / 128, B);
        scores_kernel<<<grid, 128, SMEMSZ>>>(wqh, wkh, att, mask);
    }

    // softmax
    softmax_h<<<B * S, 256>>>(att);

    // output
    {
        dim3 grid(D / 128, S / 128, B);
        out_kernel<<<grid, 128, SMEMSZ>>>(att, wvT, out);
    }
}

// round 17
// speedup vs baseline: 1.1967x; 1.0085x over previous
#include <cuda_runtime.h>
#include <cuda_fp16.h>
#include <cstdint>

// ===========================================================================
// B=8, S=2048, D=1024 attention. fp16 mma.sync(m16n8k16) + cp.async pipeline.
// R16: out_kernel consumes wv in native [k][n] layout via ldmatrix.trans --
//      transpose_h kernel and wvT buffer eliminated.
// ===========================================================================

static __device__ __half g_qh [8ull * 2048ull * 1024ull];
static __device__ __half g_kh [8ull * 2048ull * 1024ull];
static __device__ __half g_vh [8ull * 2048ull * 1024ull];
static __device__ __half g_Wqh[1024ull * 1024ull];
static __device__ __half g_Wkh[1024ull * 1024ull];
static __device__ __half g_Wvh[1024ull * 1024ull];
static __device__ __half g_wqh[8ull * 2048ull * 1024ull];
static __device__ __half g_wkh[8ull * 2048ull * 1024ull];
static __device__ __half g_wvh[8ull * 2048ull * 1024ull];
static __device__ __half g_att[8ull * 2048ull * 2048ull];

__device__ __forceinline__ uint32_t smem_u32(const void* p) {
    uint32_t a;
    asm("{ .reg .u64 t; cvta.to.shared.u64 t, %1; cvt.u32.u64 %0, t; }"
        : "=r"(a) : "l"(p));
    return a;
}

__device__ __forceinline__ void cp16(uint32_t s, const void* g) {
    asm volatile("cp.async.cg.shared.global [%0], [%1], 16;" :: "r"(s), "l"(g));
}
#define CP_COMMIT() asm volatile("cp.async.commit_group;" ::: "memory")
#define CP_WAIT1()  asm volatile("cp.async.wait_group 1;" ::: "memory")

#define LDSM_X4(r, a)                                                        \
    asm volatile("ldmatrix.sync.aligned.m8n8.x4.shared.b16 {%0,%1,%2,%3}, [%4];" \
        : "=r"((r)[0]), "=r"((r)[1]), "=r"((r)[2]), "=r"((r)[3]) : "r"(a))
#define LDSM_X4T(r, a)                                                       \
    asm volatile("ldmatrix.sync.aligned.m8n8.x4.trans.shared.b16 {%0,%1,%2,%3}, [%4];" \
        : "=r"((r)[0]), "=r"((r)[1]), "=r"((r)[2]), "=r"((r)[3]) : "r"(a))

__device__ __forceinline__ void mma_f16(float* d, const uint32_t* a,
                                        const uint32_t* b) {
    asm volatile(
        "mma.sync.aligned.m16n8k16.row.col.f32.f16.f16.f32 "
        "{%0,%1,%2,%3}, {%4,%5,%6,%7}, {%8,%9}, {%0,%1,%2,%3};\n"
        : "+f"(d[0]), "+f"(d[1]), "+f"(d[2]), "+f"(d[3])
        : "r"(a[0]), "r"(a[1]), "r"(a[2]), "r"(a[3]), "r"(b[0]), "r"(b[1]));
}

// SMEM: 3 stages x (A 16KB + B 16KB) = 96 KB
static constexpr int STAGE  = 32768;
static constexpr int SMEMSZ = 3 * STAGE;

// ---------------------------------------------------------------------------
// Core: C = alpha*(A @ op(B)) [+bias cols] [+mask]; fp16 tensor cores.
// A:[M,K] row-major. TRANSB=false: B [N,K] row-major (NT, non-trans ldmatrix,
// smem 128 rows x 128B). TRANSB=true: B [K,Nfull] row-major with row stride N
// (NN, trans ldmatrix, smem 64 k-rows x 256B). Same 16KB B tile either way.
// CTA 128x128, warp 64x64, K-chunk 64, 3-stage cp.async ring; fragments
// double-buffered in registers across the 4 kk sub-steps.
// ---------------------------------------------------------------------------
template <bool HOUT, bool TRANSB>
__device__ __forceinline__ void gemm_core(
    const __half* __restrict__ A, const __half* __restrict__ B,
    void* __restrict__ Cv, int N, int K, float alpha,
    const float* __restrict__ bias,
    const float* __restrict__ mask, int ldMask,
    int m0, int n0)
{
    extern __shared__ char smem[];
    const uint32_t sb = smem_u32(smem);
    const int tid  = threadIdx.x;
    const int lane = tid & 31;
    const int wid  = tid >> 5;
    const int wm   = wid & 1;
    const int wn   = wid >> 1;

    float acc[4][8][4];
#pragma unroll
    for (int i = 0; i < 4; ++i)
#pragma unroll
        for (int j = 0; j < 8; ++j)
#pragma unroll
            for (int l = 0; l < 4; ++l) acc[i][j][l] = 0.f;

    const int KT = K >> 6;

    auto stage = [&](int it) {
        const int buf = it % 3;
        const uint32_t sA = sb + buf * STAGE;
        const uint32_t sB = sA + 16384;
        const __half* Ab = A + (size_t)m0 * K + it * 64;
#pragma unroll
        for (int i = 0; i < 8; ++i) {
            const int f = tid + (i << 7);
            const int r = f >> 3, c = f & 7;
            cp16(sA + r * 128 + ((c ^ (r & 7)) << 4), Ab + (size_t)r * K + c * 8);
        }
        if (TRANSB) {
            // B chunk: 64 k-rows x 128 n-cols of [K][N]-major B
            const __half* Bb = B + (size_t)(it * 64) * N + n0;
#pragma unroll
            for (int i = 0; i < 8; ++i) {
                const int f = tid + (i << 7);
                const int r = f >> 4, c = f & 15;     // r: k-row, c: 16B chunk
                cp16(sB + r * 256 + ((c ^ (r & 7)) << 4),
                     Bb + (size_t)r * N + c * 8);
            }
        } else {
            const __half* Bb = B + (size_t)n0 * K + it * 64;
#pragma unroll
            for (int i = 0; i < 8; ++i) {
                const int f = tid + (i << 7);
                const int r = f >> 3, c = f & 7;
                cp16(sB + r * 128 + ((c ^ (r & 7)) << 4),
                     Bb + (size_t)r * K + c * 8);
            }
        }
    };

    stage(0); CP_COMMIT();
    stage(1); CP_COMMIT();

    // per-lane ldmatrix selectors
    const int rowA = (lane & 7) + ((lane >> 3) & 1) * 8;
    const int cselA = lane >> 4;
    // non-trans B (NT path)
    const int rowB = (lane & 7) + ((lane >> 4) << 3);
    const int cselB = (lane >> 3) & 1;
    // trans B (NN path): lane -> k-row within 16, n-chunk select
    const int krowT = (lane & 7) + ((lane >> 3) & 1) * 8;
    const int cselT = lane >> 4;                 // 0/1 -> n chunk pair

    uint32_t af[2][4][4], bf[2][4][4];

    auto loadB = [&](uint32_t* dst, uint32_t bB, int kk, int np) {
        if (TRANSB) {
            const int kr = kk * 16 + krowT;
            const int nc = wn * 8 + np * 2 + cselT;
            LDSM_X4T(dst, bB + kr * 256 + ((nc ^ (kr & 7)) << 4));
        } else {
            const int r = wn * 64 + np * 16 + rowB;
            const int ch = 2 * kk + cselB;
            LDSM_X4(dst, bB + r * 128 + ((ch ^ (r & 7)) << 4));
        }
    };

    for (int it = 0; it < KT; ++it) {
        CP_WAIT1();
        __syncthreads();
        if (it + 2 < KT) stage(it + 2);
        CP_COMMIT();

        const uint32_t aB = sb + (it % 3) * STAGE;
        const uint32_t bB = aB + 16384;

        // prime kk = 0 fragments
#pragma unroll
        for (int mi = 0; mi < 4; ++mi) {
            const int r = wm * 64 + mi * 16 + rowA;
            LDSM_X4(af[0][mi], aB + r * 128 + ((cselA ^ (r & 7)) << 4));
        }
#pragma unroll
        for (int np = 0; np < 4; ++np) loadB(bf[0][np], bB, 0, np);

#pragma unroll
        for (int kk = 0; kk < 4; ++kk) {
            const int cur = kk & 1, nxt = cur ^ 1;
            if (kk < 3) {                // prefetch kk+1 while mma'ing kk
                const int ch = 2 * (kk + 1);
#pragma unroll
                for (int mi = 0; mi < 4; ++mi) {
                    const int r = wm * 64 + mi * 16 + rowA;
                    LDSM_X4(af[nxt][mi],
                            aB + r * 128 + (((ch + cselA) ^ (r & 7)) << 4));
                }
#pragma unroll
                for (int np = 0; np < 4; ++np)
                    loadB(bf[nxt][np], bB, kk + 1, np);
            }
#pragma unroll
            for (int mi = 0; mi < 4; ++mi)
#pragma unroll
                for (int ni = 0; ni < 8; ++ni)
                    mma_f16(acc[mi][ni], af[cur][mi],
                            &bf[cur][ni >> 1][(ni & 1) * 2]);
        }
        // no trailing barrier: next iteration's CP_WAIT1+__syncthreads orders
        // these smem reads against the stage() that overwrites this buffer.
    }

    // ---- epilogue ----
    const int mrow = m0 + wm * 64 + (lane >> 2);
    const int ncol = n0 + wn * 64 + 2 * (lane & 3);
#pragma unroll
    for (int mi = 0; mi < 4; ++mi) {
#pragma unroll
        for (int h = 0; h < 2; ++h) {
            const int m = mrow + mi * 16 + h * 8;
#pragma unroll
            for (int ni = 0; ni < 8; ++ni) {
                const int n = ncol + ni * 8;
                float x = acc[mi][ni][h * 2 + 0] * alpha;
                float y = acc[mi][ni][h * 2 + 1] * alpha;
                if (bias) { x += bias[n]; y += bias[n + 1]; }
                if (mask) {
                    const float2 mm = *(const float2*)
                        (mask + (size_t)m * ldMask + n);
                    x += mm.x; y += mm.y;
                }
                if (HOUT) {
                    *(__half2*)((__half*)Cv + (size_t)m * N + n) =
                        __floats2half2_rn(x, y);
                } else {
                    *(float2*)((float*)Cv + (size_t)m * N + n) =
                        make_float2(x, y);
                }
            }
        }
    }
}

// ---- wrappers -------------------------------------------------------------
__global__ __launch_bounds__(128, 2)
void proj_kernel(const __half* q, const __half* k, const __half* v,
                 const __half* Wq, const __half* Wk, const __half* Wv,
                 const float* bq, const float* bk, const float* bv,
                 __half* wq, __half* wk, __half* wv)
{
    const int z = blockIdx.z;
    const __half* A = z == 0 ? q : z == 1 ? k : v;
    const __half* B = z == 0 ? Wq : z == 1 ? Wk : Wv;
    const float* bi = z == 0 ? bq : z == 1 ? bk : bv;
    __half*      C = z == 0 ? wq : z == 1 ? wk : wv;
    gemm_core<true, false>(A, B, C, 1024, 1024, 1.f, bi, nullptr, 0,
                           blockIdx.y * 128, blockIdx.x * 128);
}

__global__ __launch_bounds__(128, 2)
void scores_kernel(const __half* wq, const __half* wk, __half* att,
                   const float* mask)
{
    const size_t pS = 2048ull * 1024ull, aS = 2048ull * 2048ull;
    gemm_core<true, false>(wq + blockIdx.z * pS, wk + blockIdx.z * pS,
                           att + blockIdx.z * aS, 2048, 1024, 1.f / 32.f,
                           nullptr, mask, 2048,
                           blockIdx.y * 128, blockIdx.x * 128);
}

__global__ __launch_bounds__(128, 2)
void out_kernel(const __half* att, const __half* wv, float* out)
{
    const size_t aS = 2048ull * 2048ull, pS = 2048ull * 1024ull;
    gemm_core<false, true>(att + blockIdx.z * aS, wv + blockIdx.z * pS,
                           out + blockIdx.z * pS, 1024, 2048, 1.f,
                           nullptr, nullptr, 0,
                           blockIdx.y * 128, blockIdx.x * 128);
}

// ---- fp32 -> fp16 converts, z-batched -------------------------------------
__global__ __launch_bounds__(256)
void f2h_qkv(const float4* __restrict__ q, const float4* __restrict__ k,
             const float4* __restrict__ v, __half2* __restrict__ qh,
             __half2* __restrict__ kh, __half2* __restrict__ vh)
{
    const int z = blockIdx.z;
    const float4* src = z == 0 ? q : z == 1 ? k : v;
    __half2* dst = z == 0 ? qh : z == 1 ? kh : vh;
    const int i = blockIdx.x * 256 + threadIdx.x;
    const float4 val = src[i];
    dst[2 * i + 0] = __floats2half2_rn(val.x, val.y);
    dst[2 * i + 1] = __floats2half2_rn(val.z, val.w);
}

__global__ __launch_bounds__(256)
void f2h_w(const float4* __restrict__ Wq, const float4* __restrict__ Wk,
           const float4* __restrict__ Wv, __half2* __restrict__ Wqh,
           __half2* __restrict__ Wkh, __half2* __restrict__ Wvh)
{
    const int z = blockIdx.z;
    const float4* src = z == 0 ? Wq : z == 1 ? Wk : Wv;
    __half2* dst = z == 0 ? Wqh : z == 1 ? Wkh : Wvh;
    const int i = blockIdx.x * 256 + threadIdx.x;
    const float4 val = src[i];
    dst[2 * i + 0] = __floats2half2_rn(val.x, val.y);
    dst[2 * i + 1] = __floats2half2_rn(val.z, val.w);
}

// ---- softmax: rows of 2048 fp16, fp32 math --------------------------------
__global__ __launch_bounds__(256)
void softmax_h(__half* __restrict__ att)
{
    __half* p = att + (size_t)blockIdx.x * 2048;
    const int tid = threadIdx.x;
    const int lane = tid & 31;
    const int warp = tid >> 5;

    uint4 raw = ((const uint4*)p)[tid];      // 8 halves
    float2 f0 = __half22float2(*(__half2*)&raw.x);
    float2 f1 = __half22float2(*(__half2*)&raw.y);
    float2 f2 = __half22float2(*(__half2*)&raw.z);
    float2 f3 = __half22float2(*(__half2*)&raw.w);
    float x[8] = {f0.x, f0.y, f1.x, f1.y, f2.x, f2.y, f3.x, f3.y};

    __shared__ float sm[8];

    float mx = x[0];
#pragma unroll
    for (int i = 1; i < 8; ++i) mx = fmaxf(mx, x[i]);
#pragma unroll
    for (int o = 16; o > 0; o >>= 1)
        mx = fmaxf(mx, __shfl_xor_sync(0xffffffffu, mx, o));
    if (lane == 0) sm[warp] = mx;
    __syncthreads();
    if (tid == 0) {
        float t = sm[0];
#pragma unroll
        for (int i = 1; i < 8; ++i) t = fmaxf(t, sm[i]);
        sm[0] = t;
    }
    __syncthreads();
    mx = sm[0];
    __syncthreads();

    float s = 0.f;
#pragma unroll
    for (int i = 0; i < 8; ++i) { x[i] = __expf(x[i] - mx); s += x[i]; }
#pragma unroll
    for (int o = 16; o > 0; o >>= 1)
        s += __shfl_xor_sync(0xffffffffu, s, o);
    if (lane == 0) sm[warp] = s;
    __syncthreads();
    if (tid == 0) {
        float t = 0.f;
#pragma unroll
        for (int i = 0; i < 8; ++i) t += sm[i];
        sm[0] = t;
    }
    __syncthreads();
    const float inv = 1.f / sm[0];

    uint4 o;
    *(__half2*)&o.x = __floats2half2_rn(x[0] * inv, x[1] * inv);
    *(__half2*)&o.y = __floats2half2_rn(x[2] * inv, x[3] * inv);
    *(__half2*)&o.z = __floats2half2_rn(x[4] * inv, x[5] * inv);
    *(__half2*)&o.w = __floats2half2_rn(x[6] * inv, x[7] * inv);
    ((uint4*)p)[tid] = o;
}

// ---------------------------------------------------------------------------

extern "C" void kernel_launch(void* const* d_in, const int* in_sizes, int n_in,
                              void* d_out, int out_size)
{
    const float* q    = (const float*)d_in[0];
    const float* k    = (const float*)d_in[1];
    const float* v    = (const float*)d_in[2];
    const float* mask = (const float*)d_in[3];
    const float* Wq   = (const float*)d_in[4];
    const float* bq   = (const float*)d_in[5];
    const float* Wk   = (const float*)d_in[6];
    const float* bk   = (const float*)d_in[7];
    const float* Wv   = (const float*)d_in[8];
    const float* bv   = (const float*)d_in[9];
    float* out = (float*)d_out;

    __half *qh, *kh, *vh, *Wqh, *Wkh, *Wvh, *wqh, *wkh, *wvh, *att;
    cudaGetSymbolAddress((void**)&qh,  g_qh);
    cudaGetSymbolAddress((void**)&kh,  g_kh);
    cudaGetSymbolAddress((void**)&vh,  g_vh);
    cudaGetSymbolAddress((void**)&Wqh, g_Wqh);
    cudaGetSymbolAddress((void**)&Wkh, g_Wkh);
    cudaGetSymbolAddress((void**)&Wvh, g_Wvh);
    cudaGetSymbolAddress((void**)&wqh, g_wqh);
    cudaGetSymbolAddress((void**)&wkh, g_wkh);
    cudaGetSymbolAddress((void**)&wvh, g_wvh);
    cudaGetSymbolAddress((void**)&att, g_att);

    cudaFuncSetAttribute(proj_kernel,
        cudaFuncAttributeMaxDynamicSharedMemorySize, SMEMSZ);
    cudaFuncSetAttribute(scores_kernel,
        cudaFuncAttributeMaxDynamicSharedMemorySize, SMEMSZ);
    cudaFuncSetAttribute(out_kernel,
        cudaFuncAttributeMaxDynamicSharedMemorySize, SMEMSZ);

    const int B = 8, S = 2048, D = 1024;
    const int BSD4 = B * S * D / 4;
    const int DD4  = D * D / 4;

    // converts (2 z-batched launches)
    {
        dim3 grid(BSD4 / 256, 1, 3);
        f2h_qkv<<<grid, 256>>>((const float4*)q, (const float4*)k,
                               (const float4*)v,
                               (__half2*)qh, (__half2*)kh, (__half2*)vh);
    }
    {
        dim3 grid(DD4 / 256, 1, 3);
        f2h_w<<<grid, 256>>>((const float4*)Wq, (const float4*)Wk,
                             (const float4*)Wv,
                             (__half2*)Wqh, (__half2*)Wkh, (__half2*)Wvh);
    }

    // projections (z = 0,1,2)
    {
        dim3 grid(D / 128, B * S / 128, 3);
        proj_kernel<<<grid, 128, SMEMSZ>>>(qh, kh, vh, Wqh, Wkh, Wvh,
                                           bq, bk, bv, wqh, wkh, wvh);
    }

    // scores
    {
        dim3 grid(S / 128, S / 128, B);
        scores_kernel<<<grid, 128, SMEMSZ>>>(wqh, wkh, att, mask);
    }

    // softmax
    softmax_h<<<B * S, 256>>>(att);

    // output (B = wv in native [k][n] layout, trans ldmatrix)
    {
        dim3 grid(D / 128, S / 128, B);
        out_kernel<<<grid, 128, SMEMSZ>>>(att, wvh, out);
    }
}